// round 8
// baseline (speedup 1.0000x reference)
#include <cuda_runtime.h>
#include <cuda_bf16.h>
#include <math.h>
#include <stdint.h>

// Problem constants
#define Vv 50000
#define Ee 300
#define EPAD 320
#define Hh 512
#define Ll 6
#define Nn 8192
#define Kk 4
#define NCAT 2048   // [iou (1536) | f (512)] concatenated output columns

// ---------------------------------------------------------------------------
// Feature gate: tcgen05 exists only on arch-accelerated / family passes.
// ---------------------------------------------------------------------------
#if defined(__CUDA_ARCH__) && (defined(__CUDA_ARCH_FEAT_SM103_ALL) || \
    defined(__CUDA_ARCH_FEAT_SM100_ALL) || defined(__CUDA_ARCH_FEAT_SM110_ALL) || \
    (defined(__CUDA_ARCH_FAMILY_SPECIFIC__) && (__CUDA_ARCH_FAMILY_SPECIFIC__ >= 1000)))
#define USE_TCGEN05 1
#else
#define USE_TCGEN05 0
#endif

// ---------------------------------------------------------------------------
// Scratch
// ---------------------------------------------------------------------------
__device__ __nv_bfloat16 g_xhi[Ll * Nn * EPAD];   // all levels batched
__device__ __nv_bfloat16 g_xlo[Ll * Nn * EPAD];
__device__ __nv_bfloat16 g_hhi[Nn * Hh];
__device__ __nv_bfloat16 g_hlo[Nn * Hh];

__device__ __nv_bfloat16 g_WcatT_hi[NCAT * EPAD];
__device__ __nv_bfloat16 g_WcatT_lo[NCAT * EPAD];
__device__ __nv_bfloat16 g_UcatT_hi[NCAT * Hh];
__device__ __nv_bfloat16 g_UcatT_lo[NCAT * Hh];

__device__ float g_xw4all[(size_t)Ll * Nn * NCAT];  // all-level x @ [W_iou|W_f]
__device__ float g_hu4[Nn * NCAT];                  // h @ [U_iou|U_f]
__device__ float g_cbuf[2 * Nn * Hh];

// ---------------------------------------------------------------------------
// Common PTX helpers
// ---------------------------------------------------------------------------
__device__ __forceinline__ uint32_t smem_u32(const void* p) {
    uint32_t a;
    asm("{ .reg .u64 t; cvta.to.shared.u64 t, %1; cvt.u32.u64 %0, t; }"
        : "=r"(a) : "l"(p));
    return a;
}

__device__ __forceinline__ void cp16(uint32_t dst, const void* src) {
    asm volatile("cp.async.cg.shared.global [%0], [%1], 16;"
                 :: "r"(dst), "l"(src));
}

#define CP_COMMIT()  asm volatile("cp.async.commit_group;" ::: "memory")
#define CP_WAIT0()   asm volatile("cp.async.wait_group 0;" ::: "memory")
#define CP_WAIT1()   asm volatile("cp.async.wait_group 1;" ::: "memory")
#define FENCE_ASYNC() asm volatile("fence.proxy.async.shared::cta;" ::: "memory")
#define MBAR_INIT(a, cnt) \
    asm volatile("mbarrier.init.shared.b64 [%0], %1;" :: "r"(a), "r"(cnt) : "memory")

#define SW128u(o) ((uint32_t)(o) ^ ((((uint32_t)(o)) >> 3) & 0x70u))
#define DESC_BASE ((2ull << 61) | (1ull << 46) | (64ull << 32) | (1ull << 16))
#define MAKE_DESC(a) (DESC_BASE | (((uint64_t)((a) >> 4)) & 0x3FFFull))
// idesc: fp32 accum, bf16 A/B, K-major. cg2: M_total=256 (16<<24), N=256 (32<<17)
#define IDESC_CG2 (0x10u | 0x80u | 0x400u | (32u << 17) | (16u << 24))

#if USE_TCGEN05
__device__ __forceinline__ uint32_t elect1() {
    uint32_t p;
    asm volatile("{ .reg .pred p; elect.sync _|p, 0xFFFFFFFF; selp.b32 %0,1,0,p; }"
                 : "=r"(p));
    return p;
}

__device__ __forceinline__ void mbar_wait(uint32_t mbar, uint32_t parity) {
    asm volatile(
        "{\n\t.reg .pred P;\n\t"
        "WL_%=:\n\t"
        "mbarrier.try_wait.parity.acquire.cta.shared::cta.b64 P, [%0], %1, 0x989680;\n\t"
        "@P bra.uni WD_%=;\n\t"
        "bra.uni WL_%=;\n\t"
        "WD_%=:\n\t}"
        :: "r"(mbar), "r"(parity) : "memory");
}

// Cluster-scope acquire wait (consumer acquires peer-CTA forwarder's release).
__device__ __forceinline__ void mbar_wait_cluster(uint32_t mbar, uint32_t parity) {
    asm volatile(
        "{\n\t.reg .pred P;\n\t"
        "WL_%=:\n\t"
        "mbarrier.try_wait.parity.acquire.cluster.shared::cta.b64 P, [%0], %1, 0x989680;\n\t"
        "@P bra.uni WD_%=;\n\t"
        "bra.uni WL_%=;\n\t"
        "WD_%=:\n\t}"
        :: "r"(mbar), "r"(parity) : "memory");
}

// .noinc is load-bearing (R6 deadlock without it).
#define CPASYNC_MBAR_ARRIVE_NOINC(a) \
    asm volatile("cp.async.mbarrier.arrive.noinc.shared::cta.b64 [%0];" :: "r"(a) : "memory")

// Arrive on rank0's barrier at the same SMEM offset (cross-CTA).
#define MBAR_ARRIVE_RANK0(a) \
    asm volatile("{\n\t.reg .b32 ra;\n\t" \
                 "mapa.shared::cluster.u32 ra, %0, 0;\n\t" \
                 "mbarrier.arrive.shared::cluster.b64 _, [ra];\n\t}" \
                 :: "r"(a) : "memory")

#define TC_ALLOC_CG2(a, n) \
    asm volatile("tcgen05.alloc.cta_group::2.sync.aligned.shared::cta.b32 [%0], %1;" \
                 :: "r"(a), "r"(n) : "memory")
#define TC_DEALLOC_CG2(t, n) \
    asm volatile("tcgen05.dealloc.cta_group::2.sync.aligned.b32 %0, %1;" :: "r"(t), "r"(n))
#define TC_RELINQ_CG2() \
    asm volatile("tcgen05.relinquish_alloc_permit.cta_group::2.sync.aligned;")
#define TC_COMMIT_MC_CG2(m) \
    asm volatile("tcgen05.commit.cta_group::2.mbarrier::arrive::one.shared::cluster.multicast::cluster.b64 [%0], %1;" \
                 :: "r"(m), "h"((uint16_t)0x3) : "memory")
#define TC_FENCE_AFTER()  asm volatile("tcgen05.fence::after_thread_sync;" ::: "memory")
#define TC_FENCE_BEFORE() asm volatile("tcgen05.fence::before_thread_sync;" ::: "memory")
#define TC_WAIT_LD()      asm volatile("tcgen05.wait::ld.sync.aligned;" ::: "memory")
#define CLUSTER_ARRIVE()  asm volatile("barrier.cluster.arrive.aligned;" ::: "memory")
#define CLUSTER_WAIT()    asm volatile("barrier.cluster.wait.aligned;" ::: "memory")

__device__ __forceinline__ void mma_bf16_ss_cg2(uint32_t d, uint64_t ad, uint64_t bd,
                                                uint32_t idesc, uint32_t en) {
    asm volatile(
        "{\n\t.reg .pred p;\n\t"
        "setp.ne.u32 p, %4, 0;\n\t"
        "tcgen05.mma.cta_group::2.kind::f16 [%0], %1, %2, %3, {%5,%5,%5,%5,%5,%5,%5,%5}, p;\n\t}"
        :: "r"(d), "l"(ad), "l"(bd), "r"(idesc), "r"(en), "r"(0u) : "memory");
}

__device__ __forceinline__ void ldtm32(uint32_t* r, uint32_t taddr) {
    asm volatile(
        "tcgen05.ld.sync.aligned.32x32b.x32.b32 "
        "{%0, %1, %2, %3, %4, %5, %6, %7, %8, %9, %10, %11, %12, %13, %14, %15, "
        "%16, %17, %18, %19, %20, %21, %22, %23, %24, %25, %26, %27, %28, %29, %30, %31}, [%32];"
        : "=r"(r[0]), "=r"(r[1]), "=r"(r[2]), "=r"(r[3]), "=r"(r[4]), "=r"(r[5]),
          "=r"(r[6]), "=r"(r[7]), "=r"(r[8]), "=r"(r[9]), "=r"(r[10]), "=r"(r[11]),
          "=r"(r[12]), "=r"(r[13]), "=r"(r[14]), "=r"(r[15]), "=r"(r[16]), "=r"(r[17]),
          "=r"(r[18]), "=r"(r[19]), "=r"(r[20]), "=r"(r[21]), "=r"(r[22]), "=r"(r[23]),
          "=r"(r[24]), "=r"(r[25]), "=r"(r[26]), "=r"(r[27]), "=r"(r[28]), "=r"(r[29]),
          "=r"(r[30]), "=r"(r[31])
        : "r"(taddr));
}
#endif  // USE_TCGEN05

// Baseline-ISA warp MMA — fallback body
__device__ __forceinline__ void hmma16816(float* d, const uint32_t* a, const uint32_t* b) {
    asm volatile(
        "mma.sync.aligned.m16n8k16.row.col.f32.bf16.bf16.f32 "
        "{%0,%1,%2,%3}, {%4,%5,%6,%7}, {%8,%9}, {%0,%1,%2,%3};"
        : "+f"(d[0]), "+f"(d[1]), "+f"(d[2]), "+f"(d[3])
        : "r"(a[0]), "r"(a[1]), "r"(a[2]), "r"(a[3]), "r"(b[0]), "r"(b[1]));
}

__device__ __forceinline__ void split_bf16(float v, __nv_bfloat16& hi, __nv_bfloat16& lo) {
    hi = __float2bfloat16(v);
    lo = __float2bfloat16(v - __bfloat162float(hi));
}

// ---------------------------------------------------------------------------
// Weight prep: concatenated transposed split weights.
// ---------------------------------------------------------------------------
__global__ void prep_wcat_kernel(const float* __restrict__ Wa,
                                 const float* __restrict__ Wb,
                                 __nv_bfloat16* __restrict__ Thi,
                                 __nv_bfloat16* __restrict__ Tlo,
                                 int Korig, int Kpad)
{
    int idx = blockIdx.x * blockDim.x + threadIdx.x;
    if (idx >= NCAT * Kpad) return;
    int n = idx / Kpad;
    int k = idx - n * Kpad;
    float v = 0.f;
    if (k < Korig)
        v = (n < 1536) ? Wa[(size_t)k * 1536 + n] : Wb[(size_t)k * 512 + (n - 1536)];
    __nv_bfloat16 hi, lo;
    split_bf16(v, hi, lo);
    Thi[idx] = hi;
    Tlo[idx] = lo;
}

// ---------------------------------------------------------------------------
// Embedding gather + split, ALL levels in one launch
// ---------------------------------------------------------------------------
__global__ void gather_x_all_kernel(const float* __restrict__ embed,
                                    const int* __restrict__ vix,     // [L*N]
                                    const float* __restrict__ tmask, // [L*N]
                                    __nv_bfloat16* __restrict__ xhi,
                                    __nv_bfloat16* __restrict__ xlo)
{
    int idx = blockIdx.x * blockDim.x + threadIdx.x;
    const int QE = EPAD / 2;  // 160
    if (idx >= Ll * Nn * QE) return;
    int n = idx / QE;
    int e = (idx - n * QE) * 2;
    float m = tmask[n];
    float v0 = 0.f, v1 = 0.f;
    if (e < Ee) {
        const float* er = embed + (size_t)vix[n] * Ee + e;
        v0 = er[0] * m;
        v1 = er[1] * m;
    }
    __nv_bfloat16 h0, l0, h1, l1;
    split_bf16(v0, h0, l0);
    split_bf16(v1, h1, l1);
    *(__nv_bfloat162*)(xhi + (size_t)n * EPAD + e) = __nv_bfloat162(h0, h1);
    *(__nv_bfloat162*)(xlo + (size_t)n * EPAD + e) = __nv_bfloat162(l0, l1);
}

// ---------------------------------------------------------------------------
// Split-bf16 GEMM (cg2): C[M,Ncol] = (Ahi+Alo)[M,Ks] @ (Bhi+Blo)[Ncol,Ks]^T
// Cluster of 2 CTAs computes a 256(M) x 256(N) tile; each CTA loads its
// 128 M-rows of A and its 128 N-rows of B (cg2 reads B split N/2 per CTA).
// Per-CTA per-chunk traffic: 64KB per 1536-cyc MMA window (~LTS cap).
// Roles: warps 4-7 producers; warp 1 forwarder (local full -> rank0 fullX);
//        rank0 warp 0 elected consumer (cg2 MMAs + multicast commits);
//        warps 0-3 epilogue (own TMEM M-half).
// ---------------------------------------------------------------------------
#define STAGE_BYTES 65536   // Ahi 16K | Alo 16K | Bhi 16K | Blo 16K
#define GEMM_SMEM   (2 * STAGE_BYTES + 1024)

__global__ void __launch_bounds__(256) __cluster_dims__(2, 1, 1)
gemm_split_kernel(const __nv_bfloat16* __restrict__ Ahi,
                  const __nv_bfloat16* __restrict__ Alo,
                  const __nv_bfloat16* __restrict__ Bhi,
                  const __nv_bfloat16* __restrict__ Blo,
                  float* __restrict__ C,
                  int M, int Ks, int Ncol)
{
#if USE_TCGEN05
    extern __shared__ char smem_raw[];
    const uint32_t sb = smem_u32(smem_raw);
    // ctrl: [0] tmem ptr; full@16,24  empty@32,40  done@48  fullX@56,64
    const uint32_t ctrl = sb;
    const uint32_t tiles = (sb + 80 + 1023) & ~1023u;

    const int tid = threadIdx.x;
    const int wid = tid >> 5;
    const int lid = tid & 31;
    const int rank = blockIdx.x & 1;                 // cluster ctarank (dims 2,1,1 on x)
    const int n0p = (blockIdx.x >> 1) * 256;         // pair N origin
    const int m0p = blockIdx.y * 256;                // pair M origin
    const int m0 = m0p + rank * 128;                 // this CTA's M rows
    const int nB = n0p + rank * 128;                 // this CTA's B rows (N-half)
    const int NC = Ks >> 6;

    // Leaf-level f-block tiles are never read (leaf node_update uses iou only)
    if (M == Ll * Nn && n0p >= 1536 && m0p >= 5 * Nn) return;

    if (wid == 0) TC_ALLOC_CG2(ctrl, 256);
    if (tid == 0) {
        MBAR_INIT(ctrl + 16, 128);  // full[0]  local producers
        MBAR_INIT(ctrl + 24, 128);  // full[1]
        MBAR_INIT(ctrl + 32, 1);    // empty[0] (multicast commit)
        MBAR_INIT(ctrl + 40, 1);    // empty[1]
        MBAR_INIT(ctrl + 48, 1);    // done     (multicast commit)
        MBAR_INIT(ctrl + 56, 2);    // fullX[0] (both forwarders, rank0 only used)
        MBAR_INIT(ctrl + 64, 2);    // fullX[1]
    }
    __syncthreads();
    // Both CTAs' barriers must be live before any cross-CTA arrival.
    CLUSTER_ARRIVE();
    CLUSTER_WAIT();

    uint32_t tmem;
    asm("ld.shared.b32 %0, [%1];" : "=r"(tmem) : "r"(ctrl));

    if (wid >= 4) {
        // ------------------- producers (128 threads) -------------------
        const int p = tid - 128;
        for (int c = 0; c < NC; c++) {
            const int s = c & 1;
            const uint32_t ph = 1u ^ ((uint32_t)(c >> 1) & 1u);
            mbar_wait(ctrl + 32 + s * 8, ph);   // fresh-barrier pass on first use
            const uint32_t tb = tiles + s * STAGE_BYTES;
            const int k0 = c * 64;
#pragma unroll
            for (int q = p; q < 1024; q += 128) {          // A: 128 rows x 8 cols
                int row = q >> 3;
                int cc = q & 7;
                uint32_t soff = SW128u(row * 128 + cc * 16);
                size_t ao = (size_t)(m0 + row) * Ks + k0 + cc * 8;
                cp16(tb + soff,         Ahi + ao);
                cp16(tb + 16384 + soff, Alo + ao);
            }
#pragma unroll
            for (int q = p; q < 1024; q += 128) {          // B: this CTA's 128 rows
                int row = q >> 3;
                int cc = q & 7;
                uint32_t soff = SW128u(row * 128 + cc * 16);
                size_t bo = (size_t)(nB + row) * Ks + k0 + cc * 8;
                cp16(tb + 32768 + soff, Bhi + bo);
                cp16(tb + 49152 + soff, Blo + bo);
            }
            CPASYNC_MBAR_ARRIVE_NOINC(ctrl + 16 + s * 8);
        }
    } else if (wid == 1) {
        // ------------------- forwarder (1 thread per CTA) -------------------
        if (elect1()) {
            for (int c = 0; c < NC; c++) {
                const int s = c & 1;
                const uint32_t ph = (uint32_t)(c >> 1) & 1u;
                mbar_wait(ctrl + 16 + s * 8, ph);   // local stage complete
                FENCE_ASYNC();                      // make cp.async data async-proxy visible
                MBAR_ARRIVE_RANK0(ctrl + 56 + s * 8);
            }
        }
    } else if (wid == 0 && rank == 0 && elect1()) {
        // ------------------- consumer (1 thread, rank 0) -------------------
        for (int c = 0; c < NC; c++) {
            const int s = c & 1;
            const uint32_t ph = (uint32_t)(c >> 1) & 1u;
            mbar_wait_cluster(ctrl + 56 + s * 8, ph);   // both CTAs' stage s ready
            const uint32_t tb = tiles + s * STAGE_BYTES;
            uint64_t dah = MAKE_DESC(tb);
            uint64_t dal = MAKE_DESC(tb + 16384);
            uint64_t dbh = MAKE_DESC(tb + 32768);
            uint64_t dbl = MAKE_DESC(tb + 49152);
#pragma unroll
            for (int ks = 0; ks < 4; ks++)
                mma_bf16_ss_cg2(tmem, dah + 2 * ks, dbh + 2 * ks, IDESC_CG2,
                                (c == 0 && ks == 0) ? 0u : 1u);
#pragma unroll
            for (int ks = 0; ks < 4; ks++)
                mma_bf16_ss_cg2(tmem, dah + 2 * ks, dbl + 2 * ks, IDESC_CG2, 1u);
#pragma unroll
            for (int ks = 0; ks < 4; ks++)
                mma_bf16_ss_cg2(tmem, dal + 2 * ks, dbh + 2 * ks, IDESC_CG2, 1u);
            // multicast commit recycles stage s in BOTH CTAs (or gates epilogues)
            TC_COMMIT_MC_CG2((c == NC - 1) ? (ctrl + 48) : (ctrl + 32 + s * 8));
        }
    }

    // ------------------- epilogue (warps 0-3, both CTAs) -------------------
    if (wid < 4) {
        mbar_wait(ctrl + 48, 0);
        TC_FENCE_AFTER();
        float* crow = C + (size_t)(m0 + wid * 32 + lid) * Ncol + n0p;
#pragma unroll
        for (int b = 0; b < 8; b++) {
            uint32_t r[32];
            ldtm32(r, tmem + b * 32);
            TC_WAIT_LD();
#pragma unroll
            for (int j = 0; j < 32; j += 4) {
                float4 v;
                v.x = __uint_as_float(r[j + 0]);
                v.y = __uint_as_float(r[j + 1]);
                v.z = __uint_as_float(r[j + 2]);
                v.w = __uint_as_float(r[j + 3]);
                *(float4*)(crow + b * 32 + j) = v;
            }
        }
        TC_FENCE_BEFORE();
    }

    __syncthreads();
    if (wid == 0) {
        TC_RELINQ_CG2();
        TC_DEALLOC_CG2(tmem, 256);
    }
    CLUSTER_ARRIVE();
    CLUSTER_WAIT();

#else  // ------------------------- mma.sync fallback -------------------------
    extern __shared__ char smem_raw[];
    const int tid = threadIdx.x;
    const int wid = tid >> 5;
    const int lane = tid & 31;
    const int wm = wid >> 1;
    const int wn = wid & 1;
    const int r4 = lane >> 2;
    const int tig = lane & 3;
    const int rank = blockIdx.x & 1;
    const int m0 = blockIdx.y * 256 + rank * 128;
    const int NC = Ks >> 5;

    if (M == Ll * Nn && ((blockIdx.x >> 1) * 256) >= 1536 && (blockIdx.y * 256) >= 5 * Nn)
        return;

    for (int half = 0; half < 2; half++) {
        const int n0 = (blockIdx.x >> 1) * 256 + half * 128;

        float acc[2][8][4];
#pragma unroll
        for (int i = 0; i < 2; i++)
#pragma unroll
            for (int j = 0; j < 8; j++)
#pragma unroll
                for (int v = 0; v < 4; v++) acc[i][j][v] = 0.f;

        auto ldtile = [&](int buf, int k0) {
            uint32_t tb = smem_u32(smem_raw) + buf * 40960;
#pragma unroll
            for (int q = tid; q < 512; q += 256) {
                int row = q >> 2;
                int c = q & 3;
                uint32_t d = tb + row * 80 + c * 16;
                size_t ao = (size_t)(m0 + row) * Ks + k0 + c * 8;
                size_t bo = (size_t)(n0 + row) * Ks + k0 + c * 8;
                cp16(d,         Ahi + ao);
                cp16(d + 10240, Alo + ao);
                cp16(d + 20480, Bhi + bo);
                cp16(d + 30720, Blo + bo);
            }
            CP_COMMIT();
        };

        ldtile(0, 0);

        for (int c = 0; c < NC; c++) {
            const int cur = c & 1;
            if (c + 1 < NC) {
                ldtile(cur ^ 1, (c + 1) * 32);
                CP_WAIT1();
            } else {
                CP_WAIT0();
            }
            __syncthreads();

            const char* tb = smem_raw + cur * 40960;
#pragma unroll
            for (int kk = 0; kk < 32; kk += 16) {
                uint32_t ahi[2][4], alo[2][4], bhi[8][2], blo[8][2];
#pragma unroll
                for (int mi = 0; mi < 2; mi++) {
                    int row = wm * 32 + mi * 16 + r4;
                    int cb = (kk + tig * 2) * 2;
                    ahi[mi][0] = *(const uint32_t*)(tb + row * 80 + cb);
                    ahi[mi][1] = *(const uint32_t*)(tb + (row + 8) * 80 + cb);
                    ahi[mi][2] = *(const uint32_t*)(tb + row * 80 + cb + 16);
                    ahi[mi][3] = *(const uint32_t*)(tb + (row + 8) * 80 + cb + 16);
                    alo[mi][0] = *(const uint32_t*)(tb + 10240 + row * 80 + cb);
                    alo[mi][1] = *(const uint32_t*)(tb + 10240 + (row + 8) * 80 + cb);
                    alo[mi][2] = *(const uint32_t*)(tb + 10240 + row * 80 + cb + 16);
                    alo[mi][3] = *(const uint32_t*)(tb + 10240 + (row + 8) * 80 + cb + 16);
                }
#pragma unroll
                for (int ni = 0; ni < 8; ni++) {
                    int nr = wn * 64 + ni * 8 + r4;
                    int cb = (kk + tig * 2) * 2;
                    bhi[ni][0] = *(const uint32_t*)(tb + 20480 + nr * 80 + cb);
                    bhi[ni][1] = *(const uint32_t*)(tb + 20480 + nr * 80 + cb + 16);
                    blo[ni][0] = *(const uint32_t*)(tb + 30720 + nr * 80 + cb);
                    blo[ni][1] = *(const uint32_t*)(tb + 30720 + nr * 80 + cb + 16);
                }
#pragma unroll
                for (int mi = 0; mi < 2; mi++)
#pragma unroll
                    for (int ni = 0; ni < 8; ni++) {
                        hmma16816(acc[mi][ni], ahi[mi], bhi[ni]);
                        hmma16816(acc[mi][ni], ahi[mi], blo[ni]);
                        hmma16816(acc[mi][ni], alo[mi], bhi[ni]);
                    }
            }
            __syncthreads();
        }

#pragma unroll
        for (int mi = 0; mi < 2; mi++)
#pragma unroll
            for (int ni = 0; ni < 8; ni++) {
                int row = m0 + wm * 32 + mi * 16 + r4;
                int col = n0 + wn * 64 + ni * 8 + tig * 2;
                *(float2*)(C + (size_t)row * Ncol + col) =
                    make_float2(acc[mi][ni][0], acc[mi][ni][1]);
                *(float2*)(C + (size_t)(row + 8) * Ncol + col) =
                    make_float2(acc[mi][ni][2], acc[mi][ni][3]);
            }
        __syncthreads();
    }
#endif
}

// ---------------------------------------------------------------------------
// Node update (fused gates + output-side child gathers + h split)
// ---------------------------------------------------------------------------
__device__ __forceinline__ float sigmoidf_(float v) {
    return 1.f / (1.f + __expf(-v));
}

template <bool LEAF>
__global__ void node_update_kernel(const float* __restrict__ xw4,
                                   const float* __restrict__ hu4,
                                   const float* __restrict__ b_iou,
                                   const float* __restrict__ b_f,
                                   const int* __restrict__ cidx,
                                   const float* __restrict__ cmask,
                                   const float* __restrict__ c_prev,
                                   float* __restrict__ c_out,
                                   __nv_bfloat16* __restrict__ hhi,
                                   __nv_bfloat16* __restrict__ hlo,
                                   float* __restrict__ h_f32)   // may be null
{
    int idx = blockIdx.x * blockDim.x + threadIdx.x;   // over Nn * Hh/2
    if (idx >= Nn * (Hh / 2)) return;
    int n = idx >> 8;              // / 256
    int j = (idx & 255) * 2;

    const float* xw = xw4 + (size_t)n * NCAT;
    float2 gi = *(const float2*)(xw + j);
    float2 go = *(const float2*)(xw + 512 + j);
    float2 gu = *(const float2*)(xw + 1024 + j);
    {
        float2 b0 = *(const float2*)(b_iou + j);
        float2 b1 = *(const float2*)(b_iou + 512 + j);
        float2 b2 = *(const float2*)(b_iou + 1024 + j);
        gi.x += b0.x; gi.y += b0.y;
        go.x += b1.x; go.y += b1.y;
        gu.x += b2.x; gu.y += b2.y;
    }

    float fcx = 0.f, fcy = 0.f;
    if (!LEAF) {
        float2 bf = *(const float2*)(b_f + j);
        float2 xf = *(const float2*)(xw + 1536 + j);
        xf.x += bf.x; xf.y += bf.y;
#pragma unroll
        for (int k = 0; k < Kk; k++) {
            int ci = cidx[n * Kk + k];
            float m = cmask[n * Kk + k];
            const float* hr = hu4 + (size_t)ci * NCAT;
            float2 hi_ = *(const float2*)(hr + j);
            float2 ho_ = *(const float2*)(hr + 512 + j);
            float2 hu_ = *(const float2*)(hr + 1024 + j);
            float2 hf_ = *(const float2*)(hr + 1536 + j);
            gi.x += m * hi_.x; gi.y += m * hi_.y;
            go.x += m * ho_.x; go.y += m * ho_.y;
            gu.x += m * hu_.x; gu.y += m * hu_.y;
            float fx = sigmoidf_(xf.x + m * hf_.x);
            float fy = sigmoidf_(xf.y + m * hf_.y);
            float2 cpv = *(const float2*)(c_prev + (size_t)ci * Hh + j);
            fcx += fx * cpv.x * m;
            fcy += fy * cpv.y * m;
        }
    }

    float cx = sigmoidf_(gi.x) * tanhf(gu.x) + fcx;
    float cy = sigmoidf_(gi.y) * tanhf(gu.y) + fcy;
    *(float2*)(c_out + (size_t)n * Hh + j) = make_float2(cx, cy);

    float hx = sigmoidf_(go.x) * tanhf(cx);
    float hy = sigmoidf_(go.y) * tanhf(cy);

    __nv_bfloat16 h0, l0, h1, l1;
    split_bf16(hx, h0, l0);
    split_bf16(hy, h1, l1);
    *(__nv_bfloat162*)(hhi + (size_t)n * Hh + j) = __nv_bfloat162(h0, h1);
    *(__nv_bfloat162*)(hlo + (size_t)n * Hh + j) = __nv_bfloat162(l0, l1);
    if (h_f32)
        *(float2*)(h_f32 + (size_t)n * Hh + j) = make_float2(hx, hy);
}

// ---------------------------------------------------------------------------
// Launch
// ---------------------------------------------------------------------------
extern "C" void kernel_launch(void* const* d_in, const int* in_sizes, int n_in,
                              void* d_out, int out_size)
{
    const int*   vocab_ix   = (const int*)d_in[0];
    const int*   child_idx  = (const int*)d_in[1];
    const float* token_mask = (const float*)d_in[2];
    const float* child_mask = (const float*)d_in[3];
    const float* embed      = (const float*)d_in[4];
    const float* W_iou      = (const float*)d_in[5];   // [E, 3H]
    const float* U_iou      = (const float*)d_in[6];   // [H, 3H]
    const float* b_iou      = (const float*)d_in[7];
    const float* W_f        = (const float*)d_in[8];   // [E, H]
    const float* U_f        = (const float*)d_in[9];   // [H, H]
    const float* b_f        = (const float*)d_in[10];
    float* out = (float*)d_out;

    cudaFuncSetAttribute(gemm_split_kernel,
                         cudaFuncAttributeMaxDynamicSharedMemorySize, GEMM_SMEM);

    __nv_bfloat16 *xhi, *xlo, *hhi, *hlo;
    __nv_bfloat16 *WcatThi, *WcatTlo, *UcatThi, *UcatTlo;
    float *xw4all, *hu4, *cbuf;
    cudaGetSymbolAddress((void**)&xhi, g_xhi);
    cudaGetSymbolAddress((void**)&xlo, g_xlo);
    cudaGetSymbolAddress((void**)&hhi, g_hhi);
    cudaGetSymbolAddress((void**)&hlo, g_hlo);
    cudaGetSymbolAddress((void**)&WcatThi, g_WcatT_hi);
    cudaGetSymbolAddress((void**)&WcatTlo, g_WcatT_lo);
    cudaGetSymbolAddress((void**)&UcatThi, g_UcatT_hi);
    cudaGetSymbolAddress((void**)&UcatTlo, g_UcatT_lo);
    cudaGetSymbolAddress((void**)&xw4all, g_xw4all);
    cudaGetSymbolAddress((void**)&hu4, g_hu4);
    cudaGetSymbolAddress((void**)&cbuf, g_cbuf);

    float* cp[2] = { cbuf, cbuf + (size_t)Nn * Hh };

    const int T = 256;

    // Weight prep + all-level x gather + ALL xw4 GEMMs up front
    prep_wcat_kernel<<<(NCAT * EPAD + T - 1) / T, T>>>(W_iou, W_f, WcatThi, WcatTlo, Ee, EPAD);
    prep_wcat_kernel<<<(NCAT * Hh + T - 1) / T, T>>>(U_iou, U_f, UcatThi, UcatTlo, Hh, Hh);
    gather_x_all_kernel<<<(Ll * Nn * (EPAD / 2) + T - 1) / T, T>>>(
        embed, vocab_ix, token_mask, xhi, xlo);

    // xw4all = x(all levels) @ [W_iou | W_f]   M = 49152
    // grid: x = 2 * (NCAT/256) with cluster(2) pairs; y = M/256 pair tiles
    gemm_split_kernel<<<dim3(2 * (NCAT / 256), Ll * Nn / 256), 256, GEMM_SMEM>>>(
        xhi, xlo, WcatThi, WcatTlo, xw4all, Ll * Nn, EPAD, NCAT);

    const int nu_blocks = (Nn * (Hh / 2) + T - 1) / T;

    int cur = 0;
    for (int l = Ll - 1; l >= 0; --l) {
        const bool leaf = (l == Ll - 1);
        const int prev = cur ^ 1;

        if (!leaf) {
            // hu4 = h_prev @ [U_iou | U_f]
            gemm_split_kernel<<<dim3(2 * (NCAT / 256), Nn / 256), 256, GEMM_SMEM>>>(
                hhi, hlo, UcatThi, UcatTlo, hu4, Nn, Hh, NCAT);
        }

        const float* xw4l = xw4all + (size_t)l * Nn * NCAT;
        float* hf32 = (l == 0) ? out : nullptr;
        if (leaf) {
            node_update_kernel<true><<<nu_blocks, T>>>(
                xw4l, nullptr, b_iou, b_f,
                nullptr, nullptr, nullptr, cp[cur], hhi, hlo, hf32);
        } else {
            node_update_kernel<false><<<nu_blocks, T>>>(
                xw4l, hu4, b_iou, b_f,
                child_idx + l * Nn * Kk, child_mask + l * Nn * Kk,
                cp[prev], cp[cur], hhi, hlo, hf32);
        }
        cur ^= 1;
    }
}

// round 9
// speedup vs baseline: 1.1489x; 1.1489x over previous
#include <cuda_runtime.h>
#include <cuda_bf16.h>
#include <math.h>
#include <stdint.h>

// Problem constants
#define Vv 50000
#define Ee 300
#define EPAD 320
#define Hh 512
#define Ll 6
#define Nn 8192
#define Kk 4
#define NCAT 2048   // [iou (1536) | f (512)] concatenated output columns

// ---------------------------------------------------------------------------
// Feature gate: tcgen05 exists only on arch-accelerated / family passes.
// ---------------------------------------------------------------------------
#if defined(__CUDA_ARCH__) && (defined(__CUDA_ARCH_FEAT_SM103_ALL) || \
    defined(__CUDA_ARCH_FEAT_SM100_ALL) || defined(__CUDA_ARCH_FEAT_SM110_ALL) || \
    (defined(__CUDA_ARCH_FAMILY_SPECIFIC__) && (__CUDA_ARCH_FAMILY_SPECIFIC__ >= 1000)))
#define USE_TCGEN05 1
#else
#define USE_TCGEN05 0
#endif

// ---------------------------------------------------------------------------
// Scratch
// ---------------------------------------------------------------------------
__device__ __nv_bfloat16 g_xhi[Ll * Nn * EPAD];   // all levels batched
__device__ __nv_bfloat16 g_xlo[Ll * Nn * EPAD];
__device__ __nv_bfloat16 g_hhi[Nn * Hh];
__device__ __nv_bfloat16 g_hlo[Nn * Hh];

__device__ __nv_bfloat16 g_WcatT_hi[NCAT * EPAD];
__device__ __nv_bfloat16 g_WcatT_lo[NCAT * EPAD];
__device__ __nv_bfloat16 g_UcatT_hi[NCAT * Hh];
__device__ __nv_bfloat16 g_UcatT_lo[NCAT * Hh];

__device__ float g_xw4all[(size_t)Ll * Nn * NCAT];  // all-level x @ [W_iou|W_f]
__device__ float g_hu4[Nn * NCAT];                  // h @ [U_iou|U_f]
__device__ float g_cbuf[2 * Nn * Hh];

// ---------------------------------------------------------------------------
// Common PTX helpers
// ---------------------------------------------------------------------------
__device__ __forceinline__ uint32_t smem_u32(const void* p) {
    uint32_t a;
    asm("{ .reg .u64 t; cvta.to.shared.u64 t, %1; cvt.u32.u64 %0, t; }"
        : "=r"(a) : "l"(p));
    return a;
}

__device__ __forceinline__ void cp16(uint32_t dst, const void* src) {
    asm volatile("cp.async.cg.shared.global [%0], [%1], 16;"
                 :: "r"(dst), "l"(src));
}

#define CP_COMMIT()  asm volatile("cp.async.commit_group;" ::: "memory")
#define CP_WAIT0()   asm volatile("cp.async.wait_group 0;" ::: "memory")
#define CP_WAIT1()   asm volatile("cp.async.wait_group 1;" ::: "memory")
#define FENCE_ASYNC() asm volatile("fence.proxy.async.shared::cta;" ::: "memory")
#define MBAR_INIT(a, cnt) \
    asm volatile("mbarrier.init.shared.b64 [%0], %1;" :: "r"(a), "r"(cnt) : "memory")

// SW64 swizzle (64-byte rows, atom = 8 rows x 64B) + descriptor
#define SW64u(o) ((uint32_t)(o) ^ ((((uint32_t)(o)) >> 3) & 0x30u))
#define DESC_BASE_SW64 ((4ull << 61) | (1ull << 46) | (32ull << 32) | (1ull << 16))
#define MAKE_DESC64(a) (DESC_BASE_SW64 | (((uint64_t)((a) >> 4)) & 0x3FFFull))
// idesc: fp32 accum, bf16 A/B, K-major, M=128, N=256
#define IDESC_N256 (0x10u | 0x80u | 0x400u | (32u << 17) | (8u << 24))

#if USE_TCGEN05
__device__ __forceinline__ uint32_t elect1() {
    uint32_t p;
    asm volatile("{ .reg .pred p; elect.sync _|p, 0xFFFFFFFF; selp.b32 %0,1,0,p; }"
                 : "=r"(p));
    return p;
}

__device__ __forceinline__ void mbar_wait(uint32_t mbar, uint32_t parity) {
    asm volatile(
        "{\n\t.reg .pred P;\n\t"
        "WL_%=:\n\t"
        "mbarrier.try_wait.parity.acquire.cta.shared::cta.b64 P, [%0], %1, 0x989680;\n\t"
        "@P bra.uni WD_%=;\n\t"
        "bra.uni WL_%=;\n\t"
        "WD_%=:\n\t}"
        :: "r"(mbar), "r"(parity) : "memory");
}

// .noinc is load-bearing (R6 deadlock without it).
#define CPASYNC_MBAR_ARRIVE_NOINC(a) \
    asm volatile("cp.async.mbarrier.arrive.noinc.shared::cta.b64 [%0];" :: "r"(a) : "memory")

#define TC_ALLOC(a, n) \
    asm volatile("tcgen05.alloc.cta_group::1.sync.aligned.shared::cta.b32 [%0], %1;" \
                 :: "r"(a), "r"(n) : "memory")
#define TC_DEALLOC(t, n) \
    asm volatile("tcgen05.dealloc.cta_group::1.sync.aligned.b32 %0, %1;" :: "r"(t), "r"(n))
#define TC_RELINQ() \
    asm volatile("tcgen05.relinquish_alloc_permit.cta_group::1.sync.aligned;")
#define TC_COMMIT(m) \
    asm volatile("tcgen05.commit.cta_group::1.mbarrier::arrive::one.shared::cluster.b64 [%0];" \
                 :: "r"(m) : "memory")
#define TC_FENCE_AFTER()  asm volatile("tcgen05.fence::after_thread_sync;" ::: "memory")
#define TC_FENCE_BEFORE() asm volatile("tcgen05.fence::before_thread_sync;" ::: "memory")
#define TC_WAIT_LD()      asm volatile("tcgen05.wait::ld.sync.aligned;" ::: "memory")

__device__ __forceinline__ void mma_bf16_ss(uint32_t d, uint64_t ad, uint64_t bd,
                                            uint32_t idesc, uint32_t en) {
    asm volatile(
        "{\n\t.reg .pred p;\n\t"
        "setp.ne.u32 p, %4, 0;\n\t"
        "tcgen05.mma.cta_group::1.kind::f16 [%0], %1, %2, %3, {%5,%5,%5,%5}, p;\n\t}"
        :: "r"(d), "l"(ad), "l"(bd), "r"(idesc), "r"(en), "r"(0u) : "memory");
}

__device__ __forceinline__ void ldtm32(uint32_t* r, uint32_t taddr) {
    asm volatile(
        "tcgen05.ld.sync.aligned.32x32b.x32.b32 "
        "{%0, %1, %2, %3, %4, %5, %6, %7, %8, %9, %10, %11, %12, %13, %14, %15, "
        "%16, %17, %18, %19, %20, %21, %22, %23, %24, %25, %26, %27, %28, %29, %30, %31}, [%32];"
        : "=r"(r[0]), "=r"(r[1]), "=r"(r[2]), "=r"(r[3]), "=r"(r[4]), "=r"(r[5]),
          "=r"(r[6]), "=r"(r[7]), "=r"(r[8]), "=r"(r[9]), "=r"(r[10]), "=r"(r[11]),
          "=r"(r[12]), "=r"(r[13]), "=r"(r[14]), "=r"(r[15]), "=r"(r[16]), "=r"(r[17]),
          "=r"(r[18]), "=r"(r[19]), "=r"(r[20]), "=r"(r[21]), "=r"(r[22]), "=r"(r[23]),
          "=r"(r[24]), "=r"(r[25]), "=r"(r[26]), "=r"(r[27]), "=r"(r[28]), "=r"(r[29]),
          "=r"(r[30]), "=r"(r[31])
        : "r"(taddr));
}
#endif  // USE_TCGEN05

// Baseline-ISA warp MMA — fallback body
__device__ __forceinline__ void hmma16816(float* d, const uint32_t* a, const uint32_t* b) {
    asm volatile(
        "mma.sync.aligned.m16n8k16.row.col.f32.bf16.bf16.f32 "
        "{%0,%1,%2,%3}, {%4,%5,%6,%7}, {%8,%9}, {%0,%1,%2,%3};"
        : "+f"(d[0]), "+f"(d[1]), "+f"(d[2]), "+f"(d[3])
        : "r"(a[0]), "r"(a[1]), "r"(a[2]), "r"(a[3]), "r"(b[0]), "r"(b[1]));
}

__device__ __forceinline__ void split_bf16(float v, __nv_bfloat16& hi, __nv_bfloat16& lo) {
    hi = __float2bfloat16(v);
    lo = __float2bfloat16(v - __bfloat162float(hi));
}

// ---------------------------------------------------------------------------
// Weight prep: concatenated transposed split weights.
// ---------------------------------------------------------------------------
__global__ void prep_wcat_kernel(const float* __restrict__ Wa,
                                 const float* __restrict__ Wb,
                                 __nv_bfloat16* __restrict__ Thi,
                                 __nv_bfloat16* __restrict__ Tlo,
                                 int Korig, int Kpad)
{
    int idx = blockIdx.x * blockDim.x + threadIdx.x;
    if (idx >= NCAT * Kpad) return;
    int n = idx / Kpad;
    int k = idx - n * Kpad;
    float v = 0.f;
    if (k < Korig)
        v = (n < 1536) ? Wa[(size_t)k * 1536 + n] : Wb[(size_t)k * 512 + (n - 1536)];
    __nv_bfloat16 hi, lo;
    split_bf16(v, hi, lo);
    Thi[idx] = hi;
    Tlo[idx] = lo;
}

// ---------------------------------------------------------------------------
// Embedding gather + split, ALL levels in one launch
// ---------------------------------------------------------------------------
__global__ void gather_x_all_kernel(const float* __restrict__ embed,
                                    const int* __restrict__ vix,     // [L*N]
                                    const float* __restrict__ tmask, // [L*N]
                                    __nv_bfloat16* __restrict__ xhi,
                                    __nv_bfloat16* __restrict__ xlo)
{
    int idx = blockIdx.x * blockDim.x + threadIdx.x;
    const int QE = EPAD / 2;  // 160
    if (idx >= Ll * Nn * QE) return;
    int n = idx / QE;
    int e = (idx - n * QE) * 2;
    float m = tmask[n];
    float v0 = 0.f, v1 = 0.f;
    if (e < Ee) {
        const float* er = embed + (size_t)vix[n] * Ee + e;
        v0 = er[0] * m;
        v1 = er[1] * m;
    }
    __nv_bfloat16 h0, l0, h1, l1;
    split_bf16(v0, h0, l0);
    split_bf16(v1, h1, l1);
    *(__nv_bfloat162*)(xhi + (size_t)n * EPAD + e) = __nv_bfloat162(h0, h1);
    *(__nv_bfloat162*)(xlo + (size_t)n * EPAD + e) = __nv_bfloat162(l0, l1);
}

// ---------------------------------------------------------------------------
// Split-bf16 GEMM: C[M,Ncol] = (Ahi+Alo)[M,Ks] @ (Bhi+Blo)[Ncol,Ks]^T
// Tile: 256 (M) x 256 (N) per CTA. Two TMEM accumulator regions (cols 0-255
// for M rows 0-127, cols 256-511 for rows 128-255). K-chunks of 32, SW64
// layout (64B rows), 3-stage mbarrier pipeline, all barriers CTA-local:
//   warps 4-7 : producers (cp.async -> full[s] via arrive.noinc)
//   warp 0 e1 : consumer  (wait full -> 12 MMAs -> commit empty[s] / done)
//   warps 0-3 : epilogue  (wait done -> 2x8 LDTM -> STG)
// Per-chunk traffic 64KB per 1536-cyc MMA window = 42.6 B/cyc/SM (~LTS share).
// ---------------------------------------------------------------------------
#define STAGE_BYTES 65536   // Ahi 16K | Alo 16K | Bhi 16K | Blo 16K (256 rows x 64B each)
#define NSTAGE 3
#define GEMM_SMEM   (NSTAGE * STAGE_BYTES + 1024)

__global__ void __launch_bounds__(256)
gemm_split_kernel(const __nv_bfloat16* __restrict__ Ahi,
                  const __nv_bfloat16* __restrict__ Alo,
                  const __nv_bfloat16* __restrict__ Bhi,
                  const __nv_bfloat16* __restrict__ Blo,
                  float* __restrict__ C,
                  int M, int Ks, int Ncol)
{
#if USE_TCGEN05
    extern __shared__ char smem_raw[];
    const uint32_t sb = smem_u32(smem_raw);
    // ctrl: [0] tmem ptr; full@16,24,32  empty@40,48,56  done@64
    const uint32_t ctrl = sb;
    const uint32_t tiles = (sb + 80 + 1023) & ~1023u;

    const int tid = threadIdx.x;
    const int wid = tid >> 5;
    const int lid = tid & 31;
    const int m0 = blockIdx.y * 256;
    const int n0 = blockIdx.x * 256;
    const int NC = Ks >> 5;

    // Leaf-level f-block tiles are never read (leaf node_update uses iou only)
    if (M == Ll * Nn && n0 >= 1536 && m0 >= 5 * Nn) return;

    if (wid == 0) TC_ALLOC(ctrl, 512);
    if (tid == 0) {
        MBAR_INIT(ctrl + 16, 128);  // full[0]
        MBAR_INIT(ctrl + 24, 128);  // full[1]
        MBAR_INIT(ctrl + 32, 128);  // full[2]
        MBAR_INIT(ctrl + 40, 1);    // empty[0]
        MBAR_INIT(ctrl + 48, 1);    // empty[1]
        MBAR_INIT(ctrl + 56, 1);    // empty[2]
        MBAR_INIT(ctrl + 64, 1);    // done
    }
    __syncthreads();
    uint32_t tmem;
    asm("ld.shared.b32 %0, [%1];" : "=r"(tmem) : "r"(ctrl));

    if (wid >= 4) {
        // ------------------- producers (128 threads) -------------------
        const int p = tid - 128;
        int s = 0, it = 0;   // stage index, visit count (phase = visit parity)
        for (int c = 0; c < NC; c++) {
            const uint32_t ph = 1u ^ ((uint32_t)it & 1u);
            mbar_wait(ctrl + 40 + s * 8, ph);   // fresh-barrier pass on first visit
            const uint32_t tb = tiles + s * STAGE_BYTES;
            const int k0 = c * 32;
#pragma unroll
            for (int q = p; q < 1024; q += 128) {          // A: 256 rows x 4 cols(16B)
                int row = q >> 2;
                int cc = q & 3;
                uint32_t soff = SW64u(row * 64 + cc * 16);
                size_t ao = (size_t)(m0 + row) * Ks + k0 + cc * 8;
                cp16(tb + soff,         Ahi + ao);
                cp16(tb + 16384 + soff, Alo + ao);
            }
#pragma unroll
            for (int q = p; q < 1024; q += 128) {          // B: 256 rows x 4 cols
                int row = q >> 2;
                int cc = q & 3;
                uint32_t soff = SW64u(row * 64 + cc * 16);
                size_t bo = (size_t)(n0 + row) * Ks + k0 + cc * 8;
                cp16(tb + 32768 + soff, Bhi + bo);
                cp16(tb + 49152 + soff, Blo + bo);
            }
            CPASYNC_MBAR_ARRIVE_NOINC(ctrl + 16 + s * 8);
            if (++s == NSTAGE) { s = 0; it++; }
        }
    } else if (wid == 0 && elect1()) {
        // ------------------- consumer (1 thread) -------------------
        int s = 0, it = 0;
        for (int c = 0; c < NC; c++) {
            const uint32_t ph = (uint32_t)it & 1u;
            mbar_wait(ctrl + 16 + s * 8, ph);
            FENCE_ASYNC();
            const uint32_t tb = tiles + s * STAGE_BYTES;
#pragma unroll
            for (int mh = 0; mh < 2; mh++) {
                const uint32_t dtm = tmem + mh * 256;
                uint64_t dah = MAKE_DESC64(tb + mh * 8192);
                uint64_t dal = MAKE_DESC64(tb + 16384 + mh * 8192);
                uint64_t dbh = MAKE_DESC64(tb + 32768);
                uint64_t dbl = MAKE_DESC64(tb + 49152);
#pragma unroll
                for (int ks = 0; ks < 2; ks++)
                    mma_bf16_ss(dtm, dah + 2 * ks, dbh + 2 * ks, IDESC_N256,
                                (c == 0 && ks == 0) ? 0u : 1u);
#pragma unroll
                for (int ks = 0; ks < 2; ks++)
                    mma_bf16_ss(dtm, dah + 2 * ks, dbl + 2 * ks, IDESC_N256, 1u);
#pragma unroll
                for (int ks = 0; ks < 2; ks++)
                    mma_bf16_ss(dtm, dal + 2 * ks, dbh + 2 * ks, IDESC_N256, 1u);
            }
            TC_COMMIT((c == NC - 1) ? (ctrl + 64) : (ctrl + 40 + s * 8));
            if (++s == NSTAGE) { s = 0; it++; }
        }
    }

    // ------------------- epilogue (warps 0-3) -------------------
    if (wid < 4) {
        mbar_wait(ctrl + 64, 0);
        TC_FENCE_AFTER();
#pragma unroll
        for (int mh = 0; mh < 2; mh++) {
            float* crow = C + (size_t)(m0 + mh * 128 + wid * 32 + lid) * Ncol + n0;
#pragma unroll
            for (int b = 0; b < 8; b++) {
                uint32_t r[32];
                ldtm32(r, tmem + mh * 256 + b * 32);
                TC_WAIT_LD();
#pragma unroll
                for (int j = 0; j < 32; j += 4) {
                    float4 v;
                    v.x = __uint_as_float(r[j + 0]);
                    v.y = __uint_as_float(r[j + 1]);
                    v.z = __uint_as_float(r[j + 2]);
                    v.w = __uint_as_float(r[j + 3]);
                    *(float4*)(crow + b * 32 + j) = v;
                }
            }
        }
        TC_FENCE_BEFORE();
    }

    __syncthreads();
    if (wid == 0) {
        TC_RELINQ();
        TC_DEALLOC(tmem, 512);
    }

#else  // ------------------------- mma.sync fallback -------------------------
    extern __shared__ char smem_raw[];
    const int tid = threadIdx.x;
    const int wid = tid >> 5;
    const int lane = tid & 31;
    const int wm = wid >> 1;
    const int wn = wid & 1;
    const int r4 = lane >> 2;
    const int tig = lane & 3;
    const int NC = Ks >> 5;

    if (M == Ll * Nn && (blockIdx.x * 256) >= 1536 && (blockIdx.y * 256) >= 5 * Nn)
        return;

    for (int mq = 0; mq < 2; mq++) {
        const int m0 = blockIdx.y * 256 + mq * 128;
        for (int half = 0; half < 2; half++) {
            const int n0 = blockIdx.x * 256 + half * 128;

            float acc[2][8][4];
#pragma unroll
            for (int i = 0; i < 2; i++)
#pragma unroll
                for (int j = 0; j < 8; j++)
#pragma unroll
                    for (int v = 0; v < 4; v++) acc[i][j][v] = 0.f;

            auto ldtile = [&](int buf, int k0) {
                uint32_t tb = smem_u32(smem_raw) + buf * 40960;
#pragma unroll
                for (int q = tid; q < 512; q += 256) {
                    int row = q >> 2;
                    int c = q & 3;
                    uint32_t d = tb + row * 80 + c * 16;
                    size_t ao = (size_t)(m0 + row) * Ks + k0 + c * 8;
                    size_t bo = (size_t)(n0 + row) * Ks + k0 + c * 8;
                    cp16(d,         Ahi + ao);
                    cp16(d + 10240, Alo + ao);
                    cp16(d + 20480, Bhi + bo);
                    cp16(d + 30720, Blo + bo);
                }
                CP_COMMIT();
            };

            ldtile(0, 0);

            for (int c = 0; c < NC; c++) {
                const int cur = c & 1;
                if (c + 1 < NC) {
                    ldtile(cur ^ 1, (c + 1) * 32);
                    CP_WAIT1();
                } else {
                    CP_WAIT0();
                }
                __syncthreads();

                const char* tb = smem_raw + cur * 40960;
#pragma unroll
                for (int kk = 0; kk < 32; kk += 16) {
                    uint32_t ahi[2][4], alo[2][4], bhi[8][2], blo[8][2];
#pragma unroll
                    for (int mi = 0; mi < 2; mi++) {
                        int row = wm * 32 + mi * 16 + r4;
                        int cb = (kk + tig * 2) * 2;
                        ahi[mi][0] = *(const uint32_t*)(tb + row * 80 + cb);
                        ahi[mi][1] = *(const uint32_t*)(tb + (row + 8) * 80 + cb);
                        ahi[mi][2] = *(const uint32_t*)(tb + row * 80 + cb + 16);
                        ahi[mi][3] = *(const uint32_t*)(tb + (row + 8) * 80 + cb + 16);
                        alo[mi][0] = *(const uint32_t*)(tb + 10240 + row * 80 + cb);
                        alo[mi][1] = *(const uint32_t*)(tb + 10240 + (row + 8) * 80 + cb);
                        alo[mi][2] = *(const uint32_t*)(tb + 10240 + row * 80 + cb + 16);
                        alo[mi][3] = *(const uint32_t*)(tb + 10240 + (row + 8) * 80 + cb + 16);
                    }
#pragma unroll
                    for (int ni = 0; ni < 8; ni++) {
                        int nr = wn * 64 + ni * 8 + r4;
                        int cb = (kk + tig * 2) * 2;
                        bhi[ni][0] = *(const uint32_t*)(tb + 20480 + nr * 80 + cb);
                        bhi[ni][1] = *(const uint32_t*)(tb + 20480 + nr * 80 + cb + 16);
                        blo[ni][0] = *(const uint32_t*)(tb + 30720 + nr * 80 + cb);
                        blo[ni][1] = *(const uint32_t*)(tb + 30720 + nr * 80 + cb + 16);
                    }
#pragma unroll
                    for (int mi = 0; mi < 2; mi++)
#pragma unroll
                        for (int ni = 0; ni < 8; ni++) {
                            hmma16816(acc[mi][ni], ahi[mi], bhi[ni]);
                            hmma16816(acc[mi][ni], ahi[mi], blo[ni]);
                            hmma16816(acc[mi][ni], alo[mi], bhi[ni]);
                        }
                }
                __syncthreads();
            }

#pragma unroll
            for (int mi = 0; mi < 2; mi++)
#pragma unroll
                for (int ni = 0; ni < 8; ni++) {
                    int row = m0 + wm * 32 + mi * 16 + r4;
                    int col = n0 + wn * 64 + ni * 8 + tig * 2;
                    *(float2*)(C + (size_t)row * Ncol + col) =
                        make_float2(acc[mi][ni][0], acc[mi][ni][1]);
                    *(float2*)(C + (size_t)(row + 8) * Ncol + col) =
                        make_float2(acc[mi][ni][2], acc[mi][ni][3]);
                }
            __syncthreads();
        }
    }
#endif
}

// ---------------------------------------------------------------------------
// Node update (fused gates + output-side child gathers + h split)
// ---------------------------------------------------------------------------
__device__ __forceinline__ float sigmoidf_(float v) {
    return 1.f / (1.f + __expf(-v));
}

template <bool LEAF>
__global__ void node_update_kernel(const float* __restrict__ xw4,
                                   const float* __restrict__ hu4,
                                   const float* __restrict__ b_iou,
                                   const float* __restrict__ b_f,
                                   const int* __restrict__ cidx,
                                   const float* __restrict__ cmask,
                                   const float* __restrict__ c_prev,
                                   float* __restrict__ c_out,
                                   __nv_bfloat16* __restrict__ hhi,
                                   __nv_bfloat16* __restrict__ hlo,
                                   float* __restrict__ h_f32)   // may be null
{
    int idx = blockIdx.x * blockDim.x + threadIdx.x;   // over Nn * Hh/2
    if (idx >= Nn * (Hh / 2)) return;
    int n = idx >> 8;              // / 256
    int j = (idx & 255) * 2;

    const float* xw = xw4 + (size_t)n * NCAT;
    float2 gi = *(const float2*)(xw + j);
    float2 go = *(const float2*)(xw + 512 + j);
    float2 gu = *(const float2*)(xw + 1024 + j);
    {
        float2 b0 = *(const float2*)(b_iou + j);
        float2 b1 = *(const float2*)(b_iou + 512 + j);
        float2 b2 = *(const float2*)(b_iou + 1024 + j);
        gi.x += b0.x; gi.y += b0.y;
        go.x += b1.x; go.y += b1.y;
        gu.x += b2.x; gu.y += b2.y;
    }

    float fcx = 0.f, fcy = 0.f;
    if (!LEAF) {
        float2 bf = *(const float2*)(b_f + j);
        float2 xf = *(const float2*)(xw + 1536 + j);
        xf.x += bf.x; xf.y += bf.y;
#pragma unroll
        for (int k = 0; k < Kk; k++) {
            int ci = cidx[n * Kk + k];
            float m = cmask[n * Kk + k];
            const float* hr = hu4 + (size_t)ci * NCAT;
            float2 hi_ = *(const float2*)(hr + j);
            float2 ho_ = *(const float2*)(hr + 512 + j);
            float2 hu_ = *(const float2*)(hr + 1024 + j);
            float2 hf_ = *(const float2*)(hr + 1536 + j);
            gi.x += m * hi_.x; gi.y += m * hi_.y;
            go.x += m * ho_.x; go.y += m * ho_.y;
            gu.x += m * hu_.x; gu.y += m * hu_.y;
            float fx = sigmoidf_(xf.x + m * hf_.x);
            float fy = sigmoidf_(xf.y + m * hf_.y);
            float2 cpv = *(const float2*)(c_prev + (size_t)ci * Hh + j);
            fcx += fx * cpv.x * m;
            fcy += fy * cpv.y * m;
        }
    }

    float cx = sigmoidf_(gi.x) * tanhf(gu.x) + fcx;
    float cy = sigmoidf_(gi.y) * tanhf(gu.y) + fcy;
    *(float2*)(c_out + (size_t)n * Hh + j) = make_float2(cx, cy);

    float hx = sigmoidf_(go.x) * tanhf(cx);
    float hy = sigmoidf_(go.y) * tanhf(cy);

    __nv_bfloat16 h0, l0, h1, l1;
    split_bf16(hx, h0, l0);
    split_bf16(hy, h1, l1);
    *(__nv_bfloat162*)(hhi + (size_t)n * Hh + j) = __nv_bfloat162(h0, h1);
    *(__nv_bfloat162*)(hlo + (size_t)n * Hh + j) = __nv_bfloat162(l0, l1);
    if (h_f32)
        *(float2*)(h_f32 + (size_t)n * Hh + j) = make_float2(hx, hy);
}

// ---------------------------------------------------------------------------
// Launch
// ---------------------------------------------------------------------------
extern "C" void kernel_launch(void* const* d_in, const int* in_sizes, int n_in,
                              void* d_out, int out_size)
{
    const int*   vocab_ix   = (const int*)d_in[0];
    const int*   child_idx  = (const int*)d_in[1];
    const float* token_mask = (const float*)d_in[2];
    const float* child_mask = (const float*)d_in[3];
    const float* embed      = (const float*)d_in[4];
    const float* W_iou      = (const float*)d_in[5];   // [E, 3H]
    const float* U_iou      = (const float*)d_in[6];   // [H, 3H]
    const float* b_iou      = (const float*)d_in[7];
    const float* W_f        = (const float*)d_in[8];   // [E, H]
    const float* U_f        = (const float*)d_in[9];   // [H, H]
    const float* b_f        = (const float*)d_in[10];
    float* out = (float*)d_out;

    cudaFuncSetAttribute(gemm_split_kernel,
                         cudaFuncAttributeMaxDynamicSharedMemorySize, GEMM_SMEM);

    __nv_bfloat16 *xhi, *xlo, *hhi, *hlo;
    __nv_bfloat16 *WcatThi, *WcatTlo, *UcatThi, *UcatTlo;
    float *xw4all, *hu4, *cbuf;
    cudaGetSymbolAddress((void**)&xhi, g_xhi);
    cudaGetSymbolAddress((void**)&xlo, g_xlo);
    cudaGetSymbolAddress((void**)&hhi, g_hhi);
    cudaGetSymbolAddress((void**)&hlo, g_hlo);
    cudaGetSymbolAddress((void**)&WcatThi, g_WcatT_hi);
    cudaGetSymbolAddress((void**)&WcatTlo, g_WcatT_lo);
    cudaGetSymbolAddress((void**)&UcatThi, g_UcatT_hi);
    cudaGetSymbolAddress((void**)&UcatTlo, g_UcatT_lo);
    cudaGetSymbolAddress((void**)&xw4all, g_xw4all);
    cudaGetSymbolAddress((void**)&hu4, g_hu4);
    cudaGetSymbolAddress((void**)&cbuf, g_cbuf);

    float* cp[2] = { cbuf, cbuf + (size_t)Nn * Hh };

    const int T = 256;

    // Weight prep + all-level x gather + ALL xw4 GEMMs up front
    prep_wcat_kernel<<<(NCAT * EPAD + T - 1) / T, T>>>(W_iou, W_f, WcatThi, WcatTlo, Ee, EPAD);
    prep_wcat_kernel<<<(NCAT * Hh + T - 1) / T, T>>>(U_iou, U_f, UcatThi, UcatTlo, Hh, Hh);
    gather_x_all_kernel<<<(Ll * Nn * (EPAD / 2) + T - 1) / T, T>>>(
        embed, vocab_ix, token_mask, xhi, xlo);

    // xw4all = x(all levels) @ [W_iou | W_f]   M = 49152, tiles 256x256
    gemm_split_kernel<<<dim3(NCAT / 256, Ll * Nn / 256), 256, GEMM_SMEM>>>(
        xhi, xlo, WcatThi, WcatTlo, xw4all, Ll * Nn, EPAD, NCAT);

    const int nu_blocks = (Nn * (Hh / 2) + T - 1) / T;

    int cur = 0;
    for (int l = Ll - 1; l >= 0; --l) {
        const bool leaf = (l == Ll - 1);
        const int prev = cur ^ 1;

        if (!leaf) {
            // hu4 = h_prev @ [U_iou | U_f]
            gemm_split_kernel<<<dim3(NCAT / 256, Nn / 256), 256, GEMM_SMEM>>>(
                hhi, hlo, UcatThi, UcatTlo, hu4, Nn, Hh, NCAT);
        }

        const float* xw4l = xw4all + (size_t)l * Nn * NCAT;
        float* hf32 = (l == 0) ? out : nullptr;
        if (leaf) {
            node_update_kernel<true><<<nu_blocks, T>>>(
                xw4l, nullptr, b_iou, b_f,
                nullptr, nullptr, nullptr, cp[cur], hhi, hlo, hf32);
        } else {
            node_update_kernel<false><<<nu_blocks, T>>>(
                xw4l, hu4, b_iou, b_f,
                child_idx + l * Nn * Kk, child_mask + l * Nn * Kk,
                cp[prev], cp[cur], hhi, hlo, hf32);
        }
        cur ^= 1;
    }
}